// round 14
// baseline (speedup 1.0000x reference)
#include <cuda_runtime.h>
#include <math.h>
#include <stdint.h>

#define BB   2
#define NN   384
#define HIDD 128
#define NHH  8
#define ROWS (BB*NN)          // 768
#define RR   (BB*NN*NN)       // 294912
#define H_OUT_ELEMS (ROWS*HIDD)  // 98304

// ---------------- scratch (device globals; no allocation allowed) ----------
__device__ float g_h[ROWS*HIDD];
__device__ float g_Q[ROWS*HIDD];
__device__ float g_K[ROWS*HIDD];
__device__ float g_V[ROWS*HIDD];
__device__ float g_edge_attn[(size_t)RR*NHH];   // (b,i,j,h)
__device__ float g_attn_mean[RR];
__device__ float g_hW[ROWS*HIDD];

// ---------------- helpers --------------------------------------------------
__device__ __forceinline__ void mma_bf16(float* d, const uint32_t* a, const uint32_t* b) {
    asm volatile(
        "mma.sync.aligned.m16n8k16.row.col.f32.bf16.bf16.f32 "
        "{%0,%1,%2,%3}, {%4,%5,%6,%7}, {%8,%9}, {%0,%1,%2,%3};"
        : "+f"(d[0]), "+f"(d[1]), "+f"(d[2]), "+f"(d[3])
        : "r"(a[0]), "r"(a[1]), "r"(a[2]), "r"(a[3]), "r"(b[0]), "r"(b[1]));
}

#define LDSM4(r0, r1, r2, r3, addr) \
    asm volatile("ldmatrix.sync.aligned.m8n8.x4.shared.b16 {%0,%1,%2,%3}, [%4];" \
        : "=r"(r0), "=r"(r1), "=r"(r2), "=r"(r3) : "r"(addr))

__device__ __forceinline__ uint32_t pack2bf16(float lo, float hi) {
    uint32_t r;
    asm("cvt.rn.bf16x2.f32 %0, %1, %2;" : "=r"(r) : "f"(hi), "f"(lo));
    return r;
}

__device__ __forceinline__ uint32_t smem_u32(const void* p) {
    uint32_t a;
    asm("{ .reg .u64 t; cvta.to.shared.u64 t, %1; cvt.u32.u64 %0, t; }"
        : "=r"(a) : "l"(p));
    return a;
}

// ---------------- K1: h = node@Wn+bn ; Q,K,V = h@W{q,k,v}+b ----------------
__global__ void k_node_qkv(const float* __restrict__ node,
                           const float* __restrict__ Wn, const float* __restrict__ bn,
                           const float* __restrict__ Wq, const float* __restrict__ bq,
                           const float* __restrict__ Wk, const float* __restrict__ bk,
                           const float* __restrict__ Wv, const float* __restrict__ bv) {
    int row = blockIdx.x;
    int c   = threadIdx.x;
    __shared__ float x[128];
    __shared__ float hh[128];
    x[c] = node[row*128 + c];
    __syncthreads();
    {
        float a0=0.f, a1=0.f, a2=0.f, a3=0.f;
        #pragma unroll 8
        for (int k = 0; k < 128; k += 4) {
            a0 += x[k+0] * Wn[(k+0)*128 + c];
            a1 += x[k+1] * Wn[(k+1)*128 + c];
            a2 += x[k+2] * Wn[(k+2)*128 + c];
            a3 += x[k+3] * Wn[(k+3)*128 + c];
        }
        float acc = bn[c] + ((a0+a1) + (a2+a3));
        g_h[row*128 + c] = acc;
        hh[c] = acc;
    }
    __syncthreads();
    float q0=0,q1=0,q2=0,q3=0, k0=0,k1=0,k2=0,k3=0, v0=0,v1=0,v2=0,v3=0;
    #pragma unroll 4
    for (int k = 0; k < 128; k += 4) {
        float h0 = hh[k+0], h1 = hh[k+1], h2 = hh[k+2], h3 = hh[k+3];
        q0 += h0 * Wq[(k+0)*128 + c]; q1 += h1 * Wq[(k+1)*128 + c];
        q2 += h2 * Wq[(k+2)*128 + c]; q3 += h3 * Wq[(k+3)*128 + c];
        k0 += h0 * Wk[(k+0)*128 + c]; k1 += h1 * Wk[(k+1)*128 + c];
        k2 += h2 * Wk[(k+2)*128 + c]; k3 += h3 * Wk[(k+3)*128 + c];
        v0 += h0 * Wv[(k+0)*128 + c]; v1 += h1 * Wv[(k+1)*128 + c];
        v2 += h2 * Wv[(k+2)*128 + c]; v3 += h3 * Wv[(k+3)*128 + c];
    }
    g_Q[row*128 + c] = bq[c] + ((q0+q1) + (q2+q3));
    g_K[row*128 + c] = bk[c] + ((k0+k1) + (k2+k3));
    g_V[row*128 + c] = bv[c] + ((v0+v1) + (v2+v3));
}

// ---------------- K2: bf16 ldmatrix mma edge GEMM, 2 CTAs/SM ---------------
#define K2_THREADS 256
#define TM 64
#define TILES_TOTAL (RR/TM)        // 4608
#define GRID_K2 288
#define TPC (TILES_TOTAL/GRID_K2)  // 16

#define AROW 272                   // bf16 row stride in bytes (136 bf16)
#define SM_AH 0                    // A bf16: 64*272 = 17408
#define SM_BH 17408                // B bf16: 256*272 = 69632
#define SM_BE (SM_BH + 69632)
#define SM_BG (SM_BE + 512)
#define SM_K2_TOTAL (SM_BG + 512)  // 88576

__global__ __launch_bounds__(K2_THREADS, 2)
void k_edge_gemm_mma(const float* __restrict__ E,
                     const float* __restrict__ We, const float* __restrict__ be,
                     const float* __restrict__ Wg, const float* __restrict__ bg) {
    extern __shared__ char smem[];
    uint32_t sbase = smem_u32(smem);
    float* sm_be = (float*)(smem + SM_BE);
    float* sm_bg = (float*)(smem + SM_BG);

    int tid  = threadIdx.x;
    int wid  = tid >> 5;
    int lane = tid & 31;
    int gid  = lane >> 2;
    int tig  = lane & 3;
    int wm   = wid >> 2;
    int wn   = wid & 3;
    int r0   = wm * 32;
    int nc0  = wn * 32;

    if (tid < 128) { sm_be[tid] = be[tid]; sm_bg[tid] = bg[tid]; }

    for (int idx = tid; idx < 256*16; idx += K2_THREADS) {
        int n  = idx >> 4;
        int kq = idx & 15;
        const float* S = (n < 128) ? We : Wg;
        int nn = n & 127;
        uint32_t pk[4];
        #pragma unroll
        for (int e = 0; e < 4; e++) {
            float f0 = S[(kq*8 + 2*e    )*128 + nn];
            float f1 = S[(kq*8 + 2*e + 1)*128 + nn];
            pk[e] = pack2bf16(f0, f1);
        }
        *(uint4*)(smem + SM_BH + n*AROW + kq*16) = make_uint4(pk[0], pk[1], pk[2], pk[3]);
    }

    int tile0 = blockIdx.x * TPC;

    float4 R[8];
    {
        const float4* Et = (const float4*)(E + (size_t)tile0 * TM * 128);
        #pragma unroll
        for (int j = 0; j < 8; j++) R[j] = Et[tid + j*K2_THREADS];
    }

    uint32_t Ah = sbase + SM_AH;
    uint32_t Bh = sbase + SM_BH;
    uint32_t a_base0 = Ah + (uint32_t)(r0 +      (lane & 15))*AROW + (lane >> 4)*16;
    uint32_t a_base1 = Ah + (uint32_t)(r0 + 16 + (lane & 15))*AROW + (lane >> 4)*16;
    int brow = (lane & 7) + ((lane >> 4) & 1)*8;
    uint32_t boff = ((lane >> 3) & 1)*16;
    uint32_t bE_base0 = Bh + (uint32_t)(nc0      + brow)*AROW + boff;
    uint32_t bE_base1 = Bh + (uint32_t)(nc0 + 16 + brow)*AROW + boff;
    uint32_t bG_base0 = bE_base0 + 128u*AROW;
    uint32_t bG_base1 = bE_base1 + 128u*AROW;

    for (int it = 0; it < TPC; it++) {
        __syncthreads();

        #pragma unroll
        for (int j = 0; j < 8; j++) {
            int idx = tid + j*K2_THREADS;
            int m   = idx >> 5;
            int f4  = idx & 31;
            uint32_t p0 = pack2bf16(R[j].x, R[j].y);
            uint32_t p1 = pack2bf16(R[j].z, R[j].w);
            *(uint2*)(smem + SM_AH + m*AROW + f4*8) = make_uint2(p0, p1);
        }
        __syncthreads();

        if (it + 1 < TPC) {
            const float4* Et = (const float4*)(E + (size_t)(tile0 + it + 1) * TM * 128);
            #pragma unroll
            for (int j = 0; j < 8; j++) R[j] = Et[tid + j*K2_THREADS];
        }

        float accE[2][4][4], accG[2][4][4];
        #pragma unroll
        for (int mf = 0; mf < 2; mf++)
            #pragma unroll
            for (int nf = 0; nf < 4; nf++)
                #pragma unroll
                for (int q = 0; q < 4; q++) { accE[mf][nf][q] = 0.f; accG[mf][nf][q] = 0.f; }

        #pragma unroll
        for (int ks = 0; ks < 8; ks++) {
            uint32_t koff = ks*32;
            uint32_t a0[4], a1[4];
            LDSM4(a0[0], a0[1], a0[2], a0[3], a_base0 + koff);
            LDSM4(a1[0], a1[1], a1[2], a1[3], a_base1 + koff);
            uint32_t e0[4], e1[4], gg0[4], gg1[4];
            LDSM4(e0[0], e0[1], e0[2], e0[3], bE_base0 + koff);
            LDSM4(e1[0], e1[1], e1[2], e1[3], bE_base1 + koff);
            LDSM4(gg0[0], gg0[1], gg0[2], gg0[3], bG_base0 + koff);
            LDSM4(gg1[0], gg1[1], gg1[2], gg1[3], bG_base1 + koff);

            mma_bf16(accE[0][0], a0, &e0[0]);  mma_bf16(accE[0][1], a0, &e0[2]);
            mma_bf16(accE[0][2], a0, &e1[0]);  mma_bf16(accE[0][3], a0, &e1[2]);
            mma_bf16(accE[1][0], a1, &e0[0]);  mma_bf16(accE[1][1], a1, &e0[2]);
            mma_bf16(accE[1][2], a1, &e1[0]);  mma_bf16(accE[1][3], a1, &e1[2]);
            mma_bf16(accG[0][0], a0, &gg0[0]); mma_bf16(accG[0][1], a0, &gg0[2]);
            mma_bf16(accG[0][2], a0, &gg1[0]); mma_bf16(accG[0][3], a0, &gg1[2]);
            mma_bf16(accG[1][0], a1, &gg0[0]); mma_bf16(accG[1][1], a1, &gg0[2]);
            mma_bf16(accG[1][2], a1, &gg1[0]); mma_bf16(accG[1][3], a1, &gg1[2]);
        }

        float hs[2][2][2];
        #pragma unroll
        for (int a = 0; a < 2; a++)
            #pragma unroll
            for (int b2 = 0; b2 < 2; b2++) { hs[a][b2][0] = 0.f; hs[a][b2][1] = 0.f; }

        #pragma unroll
        for (int mf = 0; mf < 2; mf++)
            #pragma unroll
            for (int nf = 0; nf < 4; nf++) {
                int col0 = nc0 + nf*8 + 2*tig;
                int hl   = nf >> 1;
                float be0 = sm_be[col0], be1 = sm_be[col0+1];
                float bg0 = sm_bg[col0], bg1 = sm_bg[col0+1];
                float v00 = (accE[mf][nf][0] + be0) * (1.f/(1.f + __expf(-(accG[mf][nf][0] + bg0))));
                float v01 = (accE[mf][nf][1] + be1) * (1.f/(1.f + __expf(-(accG[mf][nf][1] + bg1))));
                float v10 = (accE[mf][nf][2] + be0) * (1.f/(1.f + __expf(-(accG[mf][nf][2] + bg0))));
                float v11 = (accE[mf][nf][3] + be1) * (1.f/(1.f + __expf(-(accG[mf][nf][3] + bg1))));
                hs[mf][0][hl] += v00 + v01;
                hs[mf][1][hl] += v10 + v11;
            }

        #pragma unroll
        for (int mf = 0; mf < 2; mf++)
            #pragma unroll
            for (int rh = 0; rh < 2; rh++)
                #pragma unroll
                for (int hl = 0; hl < 2; hl++) {
                    float v = hs[mf][rh][hl];
                    v += __shfl_xor_sync(0xffffffffu, v, 1);
                    v += __shfl_xor_sync(0xffffffffu, v, 2);
                    hs[mf][rh][hl] = v;
                }

        if (tig == 0) {
            size_t row0 = (size_t)(tile0 + it) * TM;
            #pragma unroll
            for (int mf = 0; mf < 2; mf++)
                #pragma unroll
                for (int rh = 0; rh < 2; rh++) {
                    size_t grow = row0 + r0 + mf*16 + rh*8 + gid;
                    int h0 = wn*2;
                    g_edge_attn[grow*8 + h0    ] = hs[mf][rh][0];
                    g_edge_attn[grow*8 + h0 + 1] = hs[mf][rh][1];
                }
        }
    }
}

// ---------------- K3 (fused with K4): attention + LN + hW ------------------
__global__ __launch_bounds__(384)
void k_attn_fused(const int* __restrict__ adj,
                  const float* __restrict__ Wo, const float* __restrict__ bo,
                  const float* __restrict__ g1, const float* __restrict__ be1,
                  const float* __restrict__ Weo,
                  float* __restrict__ out) {
    int bi = blockIdx.x;
    int b  = bi / NN;
    int t  = threadIdx.x;           // 0..383
    int seg = t >> 7;               // 0..2
    int c   = t & 127;
    __shared__ float q[128];
    __shared__ float p[NHH * NN];
    __shared__ float rsum[NHH];
    __shared__ float pacc[3][128];
    __shared__ float ao[128];
    __shared__ float hf[128];
    __shared__ float red[4];
    __shared__ float red2[4];

    if (t < 128) q[t] = g_Q[bi*128 + t];
    __syncthreads();

    {
        int j = t;
        float acc[8];
        #pragma unroll
        for (int h = 0; h < 8; h++) acc[h] = 0.f;
        const float4* kr = (const float4*)&g_K[(size_t)(b*NN + j)*128];
        #pragma unroll
        for (int w = 0; w < 32; w++) {
            float4 kv = kr[w];
            const float* qq = &q[w*4];
            acc[w >> 2] += kv.x*qq[0] + kv.y*qq[1] + kv.z*qq[2] + kv.w*qq[3];
        }
        int msk = adj[(size_t)bi*NN + j];
        const float* ea = &g_edge_attn[((size_t)bi*NN + j)*8];
        #pragma unroll
        for (int h = 0; h < 8; h++) {
            float s = acc[h] * 0.25f + ea[h];
            p[h*NN + j] = (msk == 0) ? -1e9f : s;
        }
    }
    __syncthreads();

    int warp = t >> 5, lane = t & 31;
    if (warp < 8) {
        float mx = -INFINITY;
        for (int j = lane; j < NN; j += 32) mx = fmaxf(mx, p[warp*NN + j]);
        #pragma unroll
        for (int o = 16; o; o >>= 1) mx = fmaxf(mx, __shfl_xor_sync(0xffffffffu, mx, o));
        float sum = 0.f;
        for (int j = lane; j < NN; j += 32) {
            float e = __expf(p[warp*NN + j] - mx);
            p[warp*NN + j] = e;
            sum += e;
        }
        #pragma unroll
        for (int o = 16; o; o >>= 1) sum += __shfl_xor_sync(0xffffffffu, sum, o);
        if (lane == 0) rsum[warp] = 1.f / sum;
    }
    __syncthreads();

    {
        int j = t;
        float am = 0.f;
        #pragma unroll
        for (int h = 0; h < 8; h++) {
            float v = p[h*NN + j] * rsum[h];
            p[h*NN + j] = v;
            am += v;
        }
        g_attn_mean[(size_t)bi*NN + j] = am * 0.125f;
    }
    __syncthreads();

    {
        int h = c >> 4;
        const float* pv = &p[h*NN + seg*128];
        const float* Vb = &g_V[(size_t)(b*NN + seg*128)*128 + c];
        float a0 = 0.f, a1 = 0.f, a2 = 0.f, a3 = 0.f;
        #pragma unroll 8
        for (int j = 0; j < 128; j += 4) {
            a0 += pv[j+0] * Vb[(j+0)*128];
            a1 += pv[j+1] * Vb[(j+1)*128];
            a2 += pv[j+2] * Vb[(j+2)*128];
            a3 += pv[j+3] * Vb[(j+3)*128];
        }
        pacc[seg][c] = (a0 + a1) + (a2 + a3);
    }
    __syncthreads();
    if (t < 128) ao[t] = pacc[0][t] + pacc[1][t] + pacc[2][t];
    __syncthreads();

    {
        int k0 = seg * 43;
        int k1 = (seg == 2) ? 128 : k0 + 43;
        float a0=0.f, a1=0.f, a2=0.f, a3=0.f;
        int k = k0;
        for (; k + 3 < k1; k += 4) {
            a0 += ao[k+0] * Wo[(k+0)*128 + c];
            a1 += ao[k+1] * Wo[(k+1)*128 + c];
            a2 += ao[k+2] * Wo[(k+2)*128 + c];
            a3 += ao[k+3] * Wo[(k+3)*128 + c];
        }
        for (; k < k1; k++) a0 += ao[k] * Wo[k*128 + c];
        pacc[seg][c] = (a0 + a1) + (a2 + a3);
    }
    __syncthreads();

    float accv = 0.f;
    if (t < 128)
        accv = bo[t] + g_h[bi*128 + t] + pacc[0][t] + pacc[1][t] + pacc[2][t];
    {
        float v1 = accv, v2 = accv * accv;
        #pragma unroll
        for (int o = 16; o; o >>= 1) {
            v1 += __shfl_xor_sync(0xffffffffu, v1, o);
            v2 += __shfl_xor_sync(0xffffffffu, v2, o);
        }
        if (t < 128 && lane == 0) { red[warp] = v1; red2[warp] = v2; }
    }
    __syncthreads();
    float m   = (red[0]  + red[1]  + red[2]  + red[3])  * (1.f/128.f);
    float msq = (red2[0] + red2[1] + red2[2] + red2[3]) * (1.f/128.f);
    float var = fmaxf(msq - m*m, 0.f);
    if (t < 128) {
        float hv = (accv - m) * rsqrtf(var + 1e-5f) * g1[t] + be1[t];
        out[bi*128 + t] = hv;
        hf[t] = hv;
    }
    __syncthreads();

    {
        int k0 = seg * 43;
        int k1 = (seg == 2) ? 128 : k0 + 43;
        float a0=0.f, a1=0.f, a2=0.f, a3=0.f;
        int k = k0;
        for (; k + 3 < k1; k += 4) {
            a0 += hf[k+0] * Weo[(k+0)*128 + c];
            a1 += hf[k+1] * Weo[(k+1)*128 + c];
            a2 += hf[k+2] * Weo[(k+2)*128 + c];
            a3 += hf[k+3] * Weo[(k+3)*128 + c];
        }
        for (; k < k1; k++) a0 += hf[k] * Weo[k*128 + c];
        pacc[seg][c] = (a0 + a1) + (a2 + a3);
    }
    __syncthreads();
    if (t < 128)
        g_hW[bi*128 + t] = pacc[0][t] + pacc[1][t] + pacc[2][t];
}

// ---------------- K6: block-per-(b,i); warps loop over j -------------------
__global__ __launch_bounds__(256)
void k_edge_out(const float* __restrict__ E, const float* __restrict__ beo,
                const float* __restrict__ g2, const float* __restrict__ be2,
                float* __restrict__ out) {
    int bi   = blockIdx.x;           // 0..767  (row = bi*NN + j)
    int b    = bi / NN;
    int warp = threadIdx.x >> 5;
    int lane = threadIdx.x & 31;

    // loop-invariant per-thread state
    float4 hi4 = ((const float4*)g_hW)[(size_t)bi*32 + lane];
    float4 bo4 = ((const float4*)beo)[lane];
    float4 gg  = ((const float4*)g2)[lane];
    float4 bb  = ((const float4*)be2)[lane];

    const float*  amp = &g_attn_mean[(size_t)bi*NN];
    const float4* Ep  = (const float4*)E + (size_t)bi*NN*32;
    float4*       Op  = (float4*)(out + H_OUT_ELEMS) + (size_t)bi*NN*32;
    const float4* hWb = (const float4*)g_hW + (size_t)(b*NN)*32;

    // software pipeline: prefetch j, compute while loading j+8
    int j = warp;
    float  am = 0.5f * amp[j];
    float4 e  = __ldcs(&Ep[(size_t)j*32 + lane]);
    float4 hj = hWb[(size_t)j*32 + lane];

    for (; j < NN; ) {
        int jn = j + 8;
        float  am_n; float4 e_n, hj_n;
        if (jn < NN) {
            am_n = 0.5f * amp[jn];
            e_n  = __ldcs(&Ep[(size_t)jn*32 + lane]);
            hj_n = hWb[(size_t)jn*32 + lane];
        }

        float vx = e.x + am*(hi4.x + hj.x) + bo4.x;
        float vy = e.y + am*(hi4.y + hj.y) + bo4.y;
        float vz = e.z + am*(hi4.z + hj.z) + bo4.z;
        float vw = e.w + am*(hi4.w + hj.w) + bo4.w;

        float s1 = (vx + vy) + (vz + vw);
        float s2 = (vx*vx + vy*vy) + (vz*vz + vw*vw);
        #pragma unroll
        for (int o = 16; o; o >>= 1) {
            s1 += __shfl_xor_sync(0xffffffffu, s1, o);
            s2 += __shfl_xor_sync(0xffffffffu, s2, o);
        }
        float m    = s1 * (1.f/128.f);
        float var  = fmaxf(s2 * (1.f/128.f) - m*m, 0.f);
        float rstd = rsqrtf(var + 1e-5f);

        float4 o4;
        o4.x = (vx - m) * rstd * gg.x + bb.x;
        o4.y = (vy - m) * rstd * gg.y + bb.y;
        o4.z = (vz - m) * rstd * gg.z + bb.z;
        o4.w = (vw - m) * rstd * gg.w + bb.w;
        __stcs(&Op[(size_t)j*32 + lane], o4);

        j = jn;
        am = am_n; e = e_n; hj = hj_n;
    }
}

// ---------------- launch ---------------------------------------------------
extern "C" void kernel_launch(void* const* d_in, const int* in_sizes, int n_in,
                              void* d_out, int out_size) {
    const float* node = (const float*)d_in[0];
    const float* edge = (const float*)d_in[1];
    const int*   adj  = (const int*)  d_in[2];
    const float* Wn  = (const float*)d_in[3];  const float* bn  = (const float*)d_in[4];
    const float* Wq  = (const float*)d_in[5];  const float* bq  = (const float*)d_in[6];
    const float* Wk  = (const float*)d_in[7];  const float* bk  = (const float*)d_in[8];
    const float* Wv  = (const float*)d_in[9];  const float* bv  = (const float*)d_in[10];
    const float* We  = (const float*)d_in[11]; const float* be  = (const float*)d_in[12];
    const float* Wg  = (const float*)d_in[13]; const float* bg  = (const float*)d_in[14];
    const float* Wo  = (const float*)d_in[15]; const float* bo  = (const float*)d_in[16];
    const float* Weo = (const float*)d_in[17]; const float* beo = (const float*)d_in[18];
    const float* g1  = (const float*)d_in[19]; const float* be1 = (const float*)d_in[20];
    const float* g2  = (const float*)d_in[21]; const float* be2 = (const float*)d_in[22];
    float* out = (float*)d_out;

    // One-time handle creation (first call = correctness run, before the
    // harness's pre-capture baseline) so capture allocates nothing.
    static cudaStream_t s2 = 0;
    static cudaEvent_t evFork = 0, evK1 = 0;
    if (s2 == 0) {
        cudaStreamCreateWithFlags(&s2, cudaStreamNonBlocking);
        cudaEventCreateWithFlags(&evFork, cudaEventDisableTiming);
        cudaEventCreateWithFlags(&evK1,   cudaEventDisableTiming);
        cudaFuncSetAttribute(k_edge_gemm_mma,
                             cudaFuncAttributeMaxDynamicSharedMemorySize, SM_K2_TOTAL);
    }

    cudaEventRecord(evFork, 0);
    cudaStreamWaitEvent(s2, evFork, 0);

    // K1 under K2's shadow
    k_node_qkv<<<ROWS, 128, 0, s2>>>(node, Wn, bn, Wq, bq, Wk, bk, Wv, bv);
    cudaEventRecord(evK1, s2);

    // Full K2, grid 288 (2 CTA/SM)
    k_edge_gemm_mma<<<GRID_K2, K2_THREADS, SM_K2_TOTAL>>>(edge, We, be, Wg, bg);

    cudaStreamWaitEvent(0, evK1, 0);
    k_attn_fused<<<ROWS, 384>>>(adj, Wo, bo, g1, be1, Weo, out);
    k_edge_out<<<ROWS, 256>>>(edge, beo, g2, be2, out);
}

// round 15
// speedup vs baseline: 1.0505x; 1.0505x over previous
#include <cuda_runtime.h>
#include <math.h>
#include <stdint.h>

#define BB   2
#define NN   384
#define HIDD 128
#define NHH  8
#define ROWS (BB*NN)          // 768
#define RR   (BB*NN*NN)       // 294912
#define H_OUT_ELEMS (ROWS*HIDD)  // 98304

// ---------------- scratch (device globals; no allocation allowed) ----------
__device__ float g_h[ROWS*HIDD];
__device__ float g_Q[ROWS*HIDD];
__device__ float g_K[ROWS*HIDD];
__device__ float g_V[ROWS*HIDD];
__device__ float g_edge_attn[(size_t)RR*NHH];   // (b,i,j,h)
__device__ float g_attn_mean[RR];
__device__ float g_hW[ROWS*HIDD];

// ---------------- helpers --------------------------------------------------
__device__ __forceinline__ void mma_bf16(float* d, const uint32_t* a, const uint32_t* b) {
    asm volatile(
        "mma.sync.aligned.m16n8k16.row.col.f32.bf16.bf16.f32 "
        "{%0,%1,%2,%3}, {%4,%5,%6,%7}, {%8,%9}, {%0,%1,%2,%3};"
        : "+f"(d[0]), "+f"(d[1]), "+f"(d[2]), "+f"(d[3])
        : "r"(a[0]), "r"(a[1]), "r"(a[2]), "r"(a[3]), "r"(b[0]), "r"(b[1]));
}

#define LDSM4(r0, r1, r2, r3, addr) \
    asm volatile("ldmatrix.sync.aligned.m8n8.x4.shared.b16 {%0,%1,%2,%3}, [%4];" \
        : "=r"(r0), "=r"(r1), "=r"(r2), "=r"(r3) : "r"(addr))

__device__ __forceinline__ uint32_t pack2bf16(float lo, float hi) {
    uint32_t r;
    asm("cvt.rn.bf16x2.f32 %0, %1, %2;" : "=r"(r) : "f"(hi), "f"(lo));
    return r;
}

__device__ __forceinline__ uint32_t smem_u32(const void* p) {
    uint32_t a;
    asm("{ .reg .u64 t; cvta.to.shared.u64 t, %1; cvt.u32.u64 %0, t; }"
        : "=r"(a) : "l"(p));
    return a;
}

// ---------------- K1: h = node@Wn+bn ; Q,K,V = h@W{q,k,v}+b ----------------
__global__ void k_node_qkv(const float* __restrict__ node,
                           const float* __restrict__ Wn, const float* __restrict__ bn,
                           const float* __restrict__ Wq, const float* __restrict__ bq,
                           const float* __restrict__ Wk, const float* __restrict__ bk,
                           const float* __restrict__ Wv, const float* __restrict__ bv) {
    int row = blockIdx.x;
    int c   = threadIdx.x;
    __shared__ float x[128];
    __shared__ float hh[128];
    x[c] = node[row*128 + c];
    __syncthreads();
    {
        float a0=0.f, a1=0.f, a2=0.f, a3=0.f;
        #pragma unroll 8
        for (int k = 0; k < 128; k += 4) {
            a0 += x[k+0] * Wn[(k+0)*128 + c];
            a1 += x[k+1] * Wn[(k+1)*128 + c];
            a2 += x[k+2] * Wn[(k+2)*128 + c];
            a3 += x[k+3] * Wn[(k+3)*128 + c];
        }
        float acc = bn[c] + ((a0+a1) + (a2+a3));
        g_h[row*128 + c] = acc;
        hh[c] = acc;
    }
    __syncthreads();
    float q0=0,q1=0,q2=0,q3=0, k0=0,k1=0,k2=0,k3=0, v0=0,v1=0,v2=0,v3=0;
    #pragma unroll 4
    for (int k = 0; k < 128; k += 4) {
        float h0 = hh[k+0], h1 = hh[k+1], h2 = hh[k+2], h3 = hh[k+3];
        q0 += h0 * Wq[(k+0)*128 + c]; q1 += h1 * Wq[(k+1)*128 + c];
        q2 += h2 * Wq[(k+2)*128 + c]; q3 += h3 * Wq[(k+3)*128 + c];
        k0 += h0 * Wk[(k+0)*128 + c]; k1 += h1 * Wk[(k+1)*128 + c];
        k2 += h2 * Wk[(k+2)*128 + c]; k3 += h3 * Wk[(k+3)*128 + c];
        v0 += h0 * Wv[(k+0)*128 + c]; v1 += h1 * Wv[(k+1)*128 + c];
        v2 += h2 * Wv[(k+2)*128 + c]; v3 += h3 * Wv[(k+3)*128 + c];
    }
    g_Q[row*128 + c] = bq[c] + ((q0+q1) + (q2+q3));
    g_K[row*128 + c] = bk[c] + ((k0+k1) + (k2+k3));
    g_V[row*128 + c] = bv[c] + ((v0+v1) + (v2+v3));
}

// ---------------- K2: bf16 ldmatrix mma edge GEMM, 2 CTAs/SM ---------------
#define K2_THREADS 256
#define TM 64
#define TILES_TOTAL (RR/TM)        // 4608
#define GRID_K2 288
#define TPC (TILES_TOTAL/GRID_K2)  // 16

#define AROW 272                   // bf16 row stride in bytes (136 bf16)
#define SM_AH 0                    // A bf16: 64*272 = 17408
#define SM_BH 17408                // B bf16: 256*272 = 69632
#define SM_BE (SM_BH + 69632)
#define SM_BG (SM_BE + 512)
#define SM_K2_TOTAL (SM_BG + 512)  // 88576

__global__ __launch_bounds__(K2_THREADS, 2)
void k_edge_gemm_mma(const float* __restrict__ E,
                     const float* __restrict__ We, const float* __restrict__ be,
                     const float* __restrict__ Wg, const float* __restrict__ bg) {
    extern __shared__ char smem[];
    uint32_t sbase = smem_u32(smem);
    float* sm_be = (float*)(smem + SM_BE);
    float* sm_bg = (float*)(smem + SM_BG);

    int tid  = threadIdx.x;
    int wid  = tid >> 5;
    int lane = tid & 31;
    int gid  = lane >> 2;
    int tig  = lane & 3;
    int wm   = wid >> 2;
    int wn   = wid & 3;
    int r0   = wm * 32;
    int nc0  = wn * 32;

    if (tid < 128) { sm_be[tid] = be[tid]; sm_bg[tid] = bg[tid]; }

    for (int idx = tid; idx < 256*16; idx += K2_THREADS) {
        int n  = idx >> 4;
        int kq = idx & 15;
        const float* S = (n < 128) ? We : Wg;
        int nn = n & 127;
        uint32_t pk[4];
        #pragma unroll
        for (int e = 0; e < 4; e++) {
            float f0 = S[(kq*8 + 2*e    )*128 + nn];
            float f1 = S[(kq*8 + 2*e + 1)*128 + nn];
            pk[e] = pack2bf16(f0, f1);
        }
        *(uint4*)(smem + SM_BH + n*AROW + kq*16) = make_uint4(pk[0], pk[1], pk[2], pk[3]);
    }

    int tile0 = blockIdx.x * TPC;

    float4 R[8];
    {
        const float4* Et = (const float4*)(E + (size_t)tile0 * TM * 128);
        #pragma unroll
        for (int j = 0; j < 8; j++) R[j] = Et[tid + j*K2_THREADS];
    }

    uint32_t Ah = sbase + SM_AH;
    uint32_t Bh = sbase + SM_BH;
    uint32_t a_base0 = Ah + (uint32_t)(r0 +      (lane & 15))*AROW + (lane >> 4)*16;
    uint32_t a_base1 = Ah + (uint32_t)(r0 + 16 + (lane & 15))*AROW + (lane >> 4)*16;
    int brow = (lane & 7) + ((lane >> 4) & 1)*8;
    uint32_t boff = ((lane >> 3) & 1)*16;
    uint32_t bE_base0 = Bh + (uint32_t)(nc0      + brow)*AROW + boff;
    uint32_t bE_base1 = Bh + (uint32_t)(nc0 + 16 + brow)*AROW + boff;
    uint32_t bG_base0 = bE_base0 + 128u*AROW;
    uint32_t bG_base1 = bE_base1 + 128u*AROW;

    for (int it = 0; it < TPC; it++) {
        __syncthreads();

        #pragma unroll
        for (int j = 0; j < 8; j++) {
            int idx = tid + j*K2_THREADS;
            int m   = idx >> 5;
            int f4  = idx & 31;
            uint32_t p0 = pack2bf16(R[j].x, R[j].y);
            uint32_t p1 = pack2bf16(R[j].z, R[j].w);
            *(uint2*)(smem + SM_AH + m*AROW + f4*8) = make_uint2(p0, p1);
        }
        __syncthreads();

        if (it + 1 < TPC) {
            const float4* Et = (const float4*)(E + (size_t)(tile0 + it + 1) * TM * 128);
            #pragma unroll
            for (int j = 0; j < 8; j++) R[j] = Et[tid + j*K2_THREADS];
        }

        float accE[2][4][4], accG[2][4][4];
        #pragma unroll
        for (int mf = 0; mf < 2; mf++)
            #pragma unroll
            for (int nf = 0; nf < 4; nf++)
                #pragma unroll
                for (int q = 0; q < 4; q++) { accE[mf][nf][q] = 0.f; accG[mf][nf][q] = 0.f; }

        #pragma unroll
        for (int ks = 0; ks < 8; ks++) {
            uint32_t koff = ks*32;
            uint32_t a0[4], a1[4];
            LDSM4(a0[0], a0[1], a0[2], a0[3], a_base0 + koff);
            LDSM4(a1[0], a1[1], a1[2], a1[3], a_base1 + koff);
            uint32_t e0[4], e1[4], gg0[4], gg1[4];
            LDSM4(e0[0], e0[1], e0[2], e0[3], bE_base0 + koff);
            LDSM4(e1[0], e1[1], e1[2], e1[3], bE_base1 + koff);
            LDSM4(gg0[0], gg0[1], gg0[2], gg0[3], bG_base0 + koff);
            LDSM4(gg1[0], gg1[1], gg1[2], gg1[3], bG_base1 + koff);

            mma_bf16(accE[0][0], a0, &e0[0]);  mma_bf16(accE[0][1], a0, &e0[2]);
            mma_bf16(accE[0][2], a0, &e1[0]);  mma_bf16(accE[0][3], a0, &e1[2]);
            mma_bf16(accE[1][0], a1, &e0[0]);  mma_bf16(accE[1][1], a1, &e0[2]);
            mma_bf16(accE[1][2], a1, &e1[0]);  mma_bf16(accE[1][3], a1, &e1[2]);
            mma_bf16(accG[0][0], a0, &gg0[0]); mma_bf16(accG[0][1], a0, &gg0[2]);
            mma_bf16(accG[0][2], a0, &gg1[0]); mma_bf16(accG[0][3], a0, &gg1[2]);
            mma_bf16(accG[1][0], a1, &gg0[0]); mma_bf16(accG[1][1], a1, &gg0[2]);
            mma_bf16(accG[1][2], a1, &gg1[0]); mma_bf16(accG[1][3], a1, &gg1[2]);
        }

        float hs[2][2][2];
        #pragma unroll
        for (int a = 0; a < 2; a++)
            #pragma unroll
            for (int b2 = 0; b2 < 2; b2++) { hs[a][b2][0] = 0.f; hs[a][b2][1] = 0.f; }

        #pragma unroll
        for (int mf = 0; mf < 2; mf++)
            #pragma unroll
            for (int nf = 0; nf < 4; nf++) {
                int col0 = nc0 + nf*8 + 2*tig;
                int hl   = nf >> 1;
                float be0 = sm_be[col0], be1 = sm_be[col0+1];
                float bg0 = sm_bg[col0], bg1 = sm_bg[col0+1];
                float v00 = (accE[mf][nf][0] + be0) * (1.f/(1.f + __expf(-(accG[mf][nf][0] + bg0))));
                float v01 = (accE[mf][nf][1] + be1) * (1.f/(1.f + __expf(-(accG[mf][nf][1] + bg1))));
                float v10 = (accE[mf][nf][2] + be0) * (1.f/(1.f + __expf(-(accG[mf][nf][2] + bg0))));
                float v11 = (accE[mf][nf][3] + be1) * (1.f/(1.f + __expf(-(accG[mf][nf][3] + bg1))));
                hs[mf][0][hl] += v00 + v01;
                hs[mf][1][hl] += v10 + v11;
            }

        #pragma unroll
        for (int mf = 0; mf < 2; mf++)
            #pragma unroll
            for (int rh = 0; rh < 2; rh++)
                #pragma unroll
                for (int hl = 0; hl < 2; hl++) {
                    float v = hs[mf][rh][hl];
                    v += __shfl_xor_sync(0xffffffffu, v, 1);
                    v += __shfl_xor_sync(0xffffffffu, v, 2);
                    hs[mf][rh][hl] = v;
                }

        if (tig == 0) {
            size_t row0 = (size_t)(tile0 + it) * TM;
            #pragma unroll
            for (int mf = 0; mf < 2; mf++)
                #pragma unroll
                for (int rh = 0; rh < 2; rh++) {
                    size_t grow = row0 + r0 + mf*16 + rh*8 + gid;
                    int h0 = wn*2;
                    g_edge_attn[grow*8 + h0    ] = hs[mf][rh][0];
                    g_edge_attn[grow*8 + h0 + 1] = hs[mf][rh][1];
                }
        }
    }
}

// ---------------- K3 (fused with K4): attention + LN + hW ------------------
__global__ __launch_bounds__(384)
void k_attn_fused(const int* __restrict__ adj,
                  const float* __restrict__ Wo, const float* __restrict__ bo,
                  const float* __restrict__ g1, const float* __restrict__ be1,
                  const float* __restrict__ Weo,
                  float* __restrict__ out) {
    int bi = blockIdx.x;
    int b  = bi / NN;
    int t  = threadIdx.x;           // 0..383
    int seg = t >> 7;               // 0..2
    int c   = t & 127;
    __shared__ float q[128];
    __shared__ float p[NHH * NN];
    __shared__ float rsum[NHH];
    __shared__ float pacc[3][128];
    __shared__ float ao[128];
    __shared__ float hf[128];
    __shared__ float red[4];
    __shared__ float red2[4];

    if (t < 128) q[t] = g_Q[bi*128 + t];
    __syncthreads();

    {
        int j = t;
        float acc[8];
        #pragma unroll
        for (int h = 0; h < 8; h++) acc[h] = 0.f;
        const float4* kr = (const float4*)&g_K[(size_t)(b*NN + j)*128];
        #pragma unroll
        for (int w = 0; w < 32; w++) {
            float4 kv = kr[w];
            const float* qq = &q[w*4];
            acc[w >> 2] += kv.x*qq[0] + kv.y*qq[1] + kv.z*qq[2] + kv.w*qq[3];
        }
        int msk = adj[(size_t)bi*NN + j];
        const float* ea = &g_edge_attn[((size_t)bi*NN + j)*8];
        #pragma unroll
        for (int h = 0; h < 8; h++) {
            float s = acc[h] * 0.25f + ea[h];
            p[h*NN + j] = (msk == 0) ? -1e9f : s;
        }
    }
    __syncthreads();

    int warp = t >> 5, lane = t & 31;
    if (warp < 8) {
        float mx = -INFINITY;
        for (int j = lane; j < NN; j += 32) mx = fmaxf(mx, p[warp*NN + j]);
        #pragma unroll
        for (int o = 16; o; o >>= 1) mx = fmaxf(mx, __shfl_xor_sync(0xffffffffu, mx, o));
        float sum = 0.f;
        for (int j = lane; j < NN; j += 32) {
            float e = __expf(p[warp*NN + j] - mx);
            p[warp*NN + j] = e;
            sum += e;
        }
        #pragma unroll
        for (int o = 16; o; o >>= 1) sum += __shfl_xor_sync(0xffffffffu, sum, o);
        if (lane == 0) rsum[warp] = 1.f / sum;
    }
    __syncthreads();

    {
        int j = t;
        float am = 0.f;
        #pragma unroll
        for (int h = 0; h < 8; h++) {
            float v = p[h*NN + j] * rsum[h];
            p[h*NN + j] = v;
            am += v;
        }
        g_attn_mean[(size_t)bi*NN + j] = am * 0.125f;
    }
    __syncthreads();

    {
        int h = c >> 4;
        const float* pv = &p[h*NN + seg*128];
        const float* Vb = &g_V[(size_t)(b*NN + seg*128)*128 + c];
        float a0 = 0.f, a1 = 0.f, a2 = 0.f, a3 = 0.f;
        #pragma unroll 8
        for (int j = 0; j < 128; j += 4) {
            a0 += pv[j+0] * Vb[(j+0)*128];
            a1 += pv[j+1] * Vb[(j+1)*128];
            a2 += pv[j+2] * Vb[(j+2)*128];
            a3 += pv[j+3] * Vb[(j+3)*128];
        }
        pacc[seg][c] = (a0 + a1) + (a2 + a3);
    }
    __syncthreads();
    if (t < 128) ao[t] = pacc[0][t] + pacc[1][t] + pacc[2][t];
    __syncthreads();

    {
        int k0 = seg * 43;
        int k1 = (seg == 2) ? 128 : k0 + 43;
        float a0=0.f, a1=0.f, a2=0.f, a3=0.f;
        int k = k0;
        for (; k + 3 < k1; k += 4) {
            a0 += ao[k+0] * Wo[(k+0)*128 + c];
            a1 += ao[k+1] * Wo[(k+1)*128 + c];
            a2 += ao[k+2] * Wo[(k+2)*128 + c];
            a3 += ao[k+3] * Wo[(k+3)*128 + c];
        }
        for (; k < k1; k++) a0 += ao[k] * Wo[k*128 + c];
        pacc[seg][c] = (a0 + a1) + (a2 + a3);
    }
    __syncthreads();

    float accv = 0.f;
    if (t < 128)
        accv = bo[t] + g_h[bi*128 + t] + pacc[0][t] + pacc[1][t] + pacc[2][t];
    {
        float v1 = accv, v2 = accv * accv;
        #pragma unroll
        for (int o = 16; o; o >>= 1) {
            v1 += __shfl_xor_sync(0xffffffffu, v1, o);
            v2 += __shfl_xor_sync(0xffffffffu, v2, o);
        }
        if (t < 128 && lane == 0) { red[warp] = v1; red2[warp] = v2; }
    }
    __syncthreads();
    float m   = (red[0]  + red[1]  + red[2]  + red[3])  * (1.f/128.f);
    float msq = (red2[0] + red2[1] + red2[2] + red2[3]) * (1.f/128.f);
    float var = fmaxf(msq - m*m, 0.f);
    if (t < 128) {
        float hv = (accv - m) * rsqrtf(var + 1e-5f) * g1[t] + be1[t];
        out[bi*128 + t] = hv;
        hf[t] = hv;
    }
    __syncthreads();

    {
        int k0 = seg * 43;
        int k1 = (seg == 2) ? 128 : k0 + 43;
        float a0=0.f, a1=0.f, a2=0.f, a3=0.f;
        int k = k0;
        for (; k + 3 < k1; k += 4) {
            a0 += hf[k+0] * Weo[(k+0)*128 + c];
            a1 += hf[k+1] * Weo[(k+1)*128 + c];
            a2 += hf[k+2] * Weo[(k+2)*128 + c];
            a3 += hf[k+3] * Weo[(k+3)*128 + c];
        }
        for (; k < k1; k++) a0 += hf[k] * Weo[k*128 + c];
        pacc[seg][c] = (a0 + a1) + (a2 + a3);
    }
    __syncthreads();
    if (t < 128)
        g_hW[bi*128 + t] = pacc[0][t] + pacc[1][t] + pacc[2][t];
}

// ---------------- K6: warp-per-4-rows (same bi); hoisted invariants --------
#define K6_RPW 4
__global__ __launch_bounds__(256)
void k_edge_out(const float* __restrict__ E, const float* __restrict__ beo,
                const float* __restrict__ g2, const float* __restrict__ be2,
                float* __restrict__ out) {
    int warpg = blockIdx.x * 8 + (threadIdx.x >> 5);
    int lane  = threadIdx.x & 31;
    size_t row0 = (size_t)warpg * K6_RPW;       // 4 | NN -> same bi for all 4
    int bi = (int)(row0 / NN);
    int b  = bi / NN;
    int j0 = (int)(row0 - (size_t)bi*NN);

    // hoisted loop-invariants (per 4 rows)
    float4 hi4 = ((const float4*)g_hW)[(size_t)bi*32 + lane];
    float4 bo4 = ((const float4*)beo)[lane];
    float4 gg  = ((const float4*)g2)[lane];
    float4 bb  = ((const float4*)be2)[lane];

    const float4* hWb = (const float4*)g_hW + (size_t)(b*NN)*32;

    // batch-issue all 12 row loads (MLP)
    float  am[K6_RPW];
    float4 e[K6_RPW], hj[K6_RPW];
    #pragma unroll
    for (int r = 0; r < K6_RPW; r++) {
        am[r] = 0.5f * g_attn_mean[row0 + r];
        e[r]  = __ldcs(&((const float4*)E)[(row0 + r)*32 + lane]);
        hj[r] = hWb[(size_t)(j0 + r)*32 + lane];
    }

    // compute 4 rows with interleaved reductions (8 independent chains)
    float vx[K6_RPW], vy[K6_RPW], vz[K6_RPW], vw[K6_RPW];
    float s1[K6_RPW], s2[K6_RPW];
    #pragma unroll
    for (int r = 0; r < K6_RPW; r++) {
        vx[r] = e[r].x + am[r]*(hi4.x + hj[r].x) + bo4.x;
        vy[r] = e[r].y + am[r]*(hi4.y + hj[r].y) + bo4.y;
        vz[r] = e[r].z + am[r]*(hi4.z + hj[r].z) + bo4.z;
        vw[r] = e[r].w + am[r]*(hi4.w + hj[r].w) + bo4.w;
        s1[r] = (vx[r] + vy[r]) + (vz[r] + vw[r]);
        s2[r] = (vx[r]*vx[r] + vy[r]*vy[r]) + (vz[r]*vz[r] + vw[r]*vw[r]);
    }
    #pragma unroll
    for (int o = 16; o; o >>= 1) {
        #pragma unroll
        for (int r = 0; r < K6_RPW; r++) {
            s1[r] += __shfl_xor_sync(0xffffffffu, s1[r], o);
            s2[r] += __shfl_xor_sync(0xffffffffu, s2[r], o);
        }
    }
    #pragma unroll
    for (int r = 0; r < K6_RPW; r++) {
        float m    = s1[r] * (1.f/128.f);
        float var  = fmaxf(s2[r] * (1.f/128.f) - m*m, 0.f);
        float rstd = rsqrtf(var + 1e-5f);
        float4 o4;
        o4.x = (vx[r] - m) * rstd * gg.x + bb.x;
        o4.y = (vy[r] - m) * rstd * gg.y + bb.y;
        o4.z = (vz[r] - m) * rstd * gg.z + bb.z;
        o4.w = (vw[r] - m) * rstd * gg.w + bb.w;
        __stcs(&((float4*)(out + H_OUT_ELEMS))[(row0 + r)*32 + lane], o4);
    }
}

// ---------------- launch ---------------------------------------------------
extern "C" void kernel_launch(void* const* d_in, const int* in_sizes, int n_in,
                              void* d_out, int out_size) {
    const float* node = (const float*)d_in[0];
    const float* edge = (const float*)d_in[1];
    const int*   adj  = (const int*)  d_in[2];
    const float* Wn  = (const float*)d_in[3];  const float* bn  = (const float*)d_in[4];
    const float* Wq  = (const float*)d_in[5];  const float* bq  = (const float*)d_in[6];
    const float* Wk  = (const float*)d_in[7];  const float* bk  = (const float*)d_in[8];
    const float* Wv  = (const float*)d_in[9];  const float* bv  = (const float*)d_in[10];
    const float* We  = (const float*)d_in[11]; const float* be  = (const float*)d_in[12];
    const float* Wg  = (const float*)d_in[13]; const float* bg  = (const float*)d_in[14];
    const float* Wo  = (const float*)d_in[15]; const float* bo  = (const float*)d_in[16];
    const float* Weo = (const float*)d_in[17]; const float* beo = (const float*)d_in[18];
    const float* g1  = (const float*)d_in[19]; const float* be1 = (const float*)d_in[20];
    const float* g2  = (const float*)d_in[21]; const float* be2 = (const float*)d_in[22];
    float* out = (float*)d_out;

    // One-time handle creation (first call = correctness run, before the
    // harness's pre-capture baseline) so capture allocates nothing.
    static cudaStream_t s2 = 0;
    static cudaEvent_t evFork = 0, evK1 = 0;
    if (s2 == 0) {
        cudaStreamCreateWithFlags(&s2, cudaStreamNonBlocking);
        cudaEventCreateWithFlags(&evFork, cudaEventDisableTiming);
        cudaEventCreateWithFlags(&evK1,   cudaEventDisableTiming);
        cudaFuncSetAttribute(k_edge_gemm_mma,
                             cudaFuncAttributeMaxDynamicSharedMemorySize, SM_K2_TOTAL);
    }

    cudaEventRecord(evFork, 0);
    cudaStreamWaitEvent(s2, evFork, 0);

    // K1 under K2's shadow
    k_node_qkv<<<ROWS, 128, 0, s2>>>(node, Wn, bn, Wq, bq, Wk, bk, Wv, bv);
    cudaEventRecord(evK1, s2);

    // Full K2, grid 288 (2 CTA/SM)
    k_edge_gemm_mma<<<GRID_K2, K2_THREADS, SM_K2_TOTAL>>>(edge, We, be, Wg, bg);

    cudaStreamWaitEvent(0, evK1, 0);
    k_attn_fused<<<ROWS, 384>>>(adj, Wo, bo, g1, be1, Weo, out);
    k_edge_out<<<RR/(8*K6_RPW), 256>>>(edge, beo, g2, be2, out);
}